// round 13
// baseline (speedup 1.0000x reference)
#include <cuda_runtime.h>
#include <cstdint>
#include <math.h>

#define T_DIM   1024
#define H_DIM   256
#define HH      128               // dims per CTA (half)
#define HH4     32                // float4 slots per half-row
#define NTHREADS 256
#define CHUNK   128               // t-rows per compute chunk
#define NCHUNK  (T_DIM / CHUNK)   // 8
#define NSTAGE  3
#define SROWS   64                // rows per stage
#define NHC     (T_DIM / SROWS)   // 16 half-chunks

#define STAGE_FLOATS (SROWS * HH)        // 8192 floats = 32 KB
#define ROW_BYTES    (HH * 4)            // 512 B per half-row

// smem floats: buf[3][8192] | sRedH[2][128] | sE[128] | sR[128] | sPart[8][32]f4
#define SMEM_FLOATS (NSTAGE * STAGE_FLOATS + 256 + 128 + 128 + 8 * HH4 * 4)
#define SMEM_BYTES  (SMEM_FLOATS * 4 + (NSTAGE + 1) * 8 + 8)

__device__ __forceinline__ uint32_t smem_u32(const void* p) {
    uint32_t a;
    asm("{ .reg .u64 t; cvta.to.shared.u64 t, %1; cvt.u32.u64 %0, t; }" : "=r"(a) : "l"(p));
    return a;
}
__device__ __forceinline__ uint32_t mapa_u32(uint32_t addr, uint32_t rank) {
    uint32_t r;
    asm("mapa.shared::cluster.u32 %0, %1, %2;" : "=r"(r) : "r"(addr), "r"(rank));
    return r;
}
__device__ __forceinline__ void mbar_init(uint32_t mbar, uint32_t count) {
    asm volatile("mbarrier.init.shared.b64 [%0], %1;" :: "r"(mbar), "r"(count) : "memory");
}
__device__ __forceinline__ void mbar_arrive_expect_tx(uint32_t mbar, uint32_t bytes) {
    asm volatile("mbarrier.arrive.expect_tx.shared.b64 _, [%0], %1;" :: "r"(mbar), "r"(bytes) : "memory");
}
__device__ __forceinline__ void bulk_g2s(uint32_t dst, const void* src, uint32_t bytes, uint32_t mbar) {
    asm volatile("cp.async.bulk.shared::cta.global.mbarrier::complete_tx::bytes [%0], [%1], %2, [%3];"
                 :: "r"(dst), "l"(src), "r"(bytes), "r"(mbar) : "memory");
}
__device__ __forceinline__ void st_shared_remote_f32(uint32_t addr, float v) {
    asm volatile("st.shared::cluster.f32 [%0], %1;" :: "r"(addr), "f"(v) : "memory");
}
__device__ __forceinline__ void mbar_arrive_remote(uint32_t addr) {
    asm volatile("mbarrier.arrive.release.cluster.shared::cluster.b64 _, [%0];"
                 :: "r"(addr) : "memory");
}
__device__ __forceinline__ void mbar_wait_parity_cta(uint32_t mbar, uint32_t parity) {
    uint32_t done;
    asm volatile(
        "{\n\t.reg .pred p;\n\t"
        "mbarrier.try_wait.parity.acquire.cta.shared::cta.b64 p, [%1], %2;\n\t"
        "selp.b32 %0, 1, 0, p;\n\t}"
        : "=r"(done) : "r"(mbar), "r"(parity) : "memory");
    if (!done) {
        asm volatile(
            "{\n\t.reg .pred P1;\n\t"
            "WL_%=:\n\t"
            "mbarrier.try_wait.parity.acquire.cta.shared::cta.b64 P1, [%0], %1, 0x989680;\n\t"
            "@P1 bra.uni WD_%=;\n\t"
            "bra.uni WL_%=;\n\t"
            "WD_%=:\n\t}"
            :: "r"(mbar), "r"(parity) : "memory");
    }
}
__device__ __forceinline__ void mbar_wait_parity_cluster(uint32_t mbar, uint32_t parity) {
    uint32_t done;
    asm volatile(
        "{\n\t.reg .pred p;\n\t"
        "mbarrier.try_wait.parity.acquire.cluster.shared::cta.b64 p, [%1], %2;\n\t"
        "selp.b32 %0, 1, 0, p;\n\t}"
        : "=r"(done) : "r"(mbar), "r"(parity) : "memory");
    if (!done) {
        asm volatile(
            "{\n\t.reg .pred P1;\n\t"
            "WL_%=:\n\t"
            "mbarrier.try_wait.parity.acquire.cluster.shared::cta.b64 P1, [%0], %1, 0x989680;\n\t"
            "@P1 bra.uni WD_%=;\n\t"
            "bra.uni WL_%=;\n\t"
            "WD_%=:\n\t}"
            :: "r"(mbar), "r"(parity) : "memory");
    }
}

__global__ __launch_bounds__(NTHREADS, 2) __cluster_dims__(2, 1, 1)
void temporal_attn_causal_kernel(const float* __restrict__ h,
                                 const float* __restrict__ attn_w,
                                 const float* __restrict__ attn_b,
                                 float* __restrict__ out) {
    extern __shared__ __align__(16) unsigned char smem_raw[];
    float*    buf    = (float*)smem_raw;                    // 3 x 32KB stages
    float*    sRedH  = buf + NSTAGE * STAGE_FLOATS;         // [2 half][128 row]
    float4*   sE4    = (float4*)(sRedH + 256);              // 32 quads (128 e)
    float4*   sR4    = sE4 + 32;                            // 32 quads (128 r)
    float4*   sPart4 = sR4 + 32;                            // [8 q][32 lane]
    uint64_t* smbar  = (uint64_t*)(sPart4 + 8 * HH4);       // [3] stage mbars
    uint64_t* xbar   = smbar + NSTAGE;                      // exchange mbar

    const int bl   = blockIdx.x >> 1;      // (b,l) index: 128
    const uint32_t rank = blockIdx.x & 1;  // H-half
    const uint32_t peer = rank ^ 1;
    const int tid  = threadIdx.x;
    const int lane = tid & 31;
    const int q    = tid >> 5;             // warp == t-group (16 rows each)

    // this CTA's global views: dims [rank*128, rank*128+128)
    const float* __restrict__ hb = h + (size_t)bl * T_DIM * H_DIM + rank * HH;
    float4* __restrict__ ob4 = (float4*)(out + (size_t)bl * T_DIM * H_DIM + rank * HH);

    const float4 wv = ((const float4*)attn_w)[rank * HH4 + lane];
    const float bias = attn_b[0];

    if (tid == 0) {
        #pragma unroll
        for (int s = 0; s < NSTAGE; s++) mbar_init(smem_u32(&smbar[s]), 64);
        mbar_init(smem_u32(xbar), 128);
        asm volatile("fence.proxy.async.shared::cta;" ::: "memory");
    }
    __syncthreads();
    // cluster-wide: all mbarriers initialized before any DSMEM traffic
    asm volatile("barrier.cluster.arrive.aligned;" ::: "memory");
    asm volatile("barrier.cluster.wait.aligned;" ::: "memory");

    // prologue: fill stages 0..2 (threads 0..191, one 512B row each)
    if (tid < 64 * NSTAGE) {
        const int s = tid >> 6;
        const int i = tid & 63;
        uint32_t mb = smem_u32(&smbar[s]);
        mbar_arrive_expect_tx(mb, ROW_BYTES);
        bulk_g2s(smem_u32(buf + s * STAGE_FLOATS + i * HH),
                 hb + (size_t)(s * SROWS + i) * H_DIM, ROW_BYTES, mb);
    }

    float carry = 0.f;                               // scan carry (warp 0, both CTAs identical)
    float4 accP = make_float4(0.f, 0.f, 0.f, 0.f);   // running acc for dims 4*lane.. (replicated x8 q)

    const uint32_t xbar_local = smem_u32(xbar);
    const uint32_t xbar_peer  = mapa_u32(xbar_local, peer);

    for (int g = 0; g < NCHUNK; g++) {
        const int hcA = 2 * g, hcB = 2 * g + 1;
        const int sA = hcA % 3, sB = hcB % 3;
        mbar_wait_parity_cta(smem_u32(&smbar[sA]), (uint32_t)((hcA / 3) & 1));
        mbar_wait_parity_cta(smem_u32(&smbar[sB]), (uint32_t)((hcB / 3) & 1));

        // ---- load my 16 rows x float4 (half dims) + dot partials ----
        const float4* tile4 = (const float4*)(buf + (q < 4 ? sA : sB) * STAGE_FLOATS);
        const int rowBase = (q & 3) * 16;
        float4 hv[16];
        float  p[16];
        #pragma unroll
        for (int k = 0; k < 16; k++) {
            hv[k] = tile4[(rowBase + k) * HH4 + lane];
            p[k] = hv[k].x * wv.x + hv[k].y * wv.y + hv[k].z * wv.z + hv[k].w * wv.w;
        }

        // ---- butterfly: reduce 16 k-partials over 32 lanes ----
        float rsum;
        {
            const int b0 = lane & 1, b1 = (lane >> 1) & 1,
                      b2 = (lane >> 2) & 1, b3 = (lane >> 3) & 1;
            float q0[8];
            #pragma unroll
            for (int j = 0; j < 8; j++) {
                float keep = b0 ? p[2*j+1] : p[2*j];
                float send = b0 ? p[2*j]   : p[2*j+1];
                q0[j] = keep + __shfl_xor_sync(0xffffffffu, send, 1);
            }
            float q1[4];
            #pragma unroll
            for (int j = 0; j < 4; j++) {
                float keep = b1 ? q0[2*j+1] : q0[2*j];
                float send = b1 ? q0[2*j]   : q0[2*j+1];
                q1[j] = keep + __shfl_xor_sync(0xffffffffu, send, 2);
            }
            float q2[2];
            #pragma unroll
            for (int j = 0; j < 2; j++) {
                float keep = b2 ? q1[2*j+1] : q1[2*j];
                float send = b2 ? q1[2*j]   : q1[2*j+1];
                q2[j] = keep + __shfl_xor_sync(0xffffffffu, send, 4);
            }
            float keep = b3 ? q2[1] : q2[0];
            float send = b3 ? q2[0] : q2[1];
            float q3 = keep + __shfl_xor_sync(0xffffffffu, send, 8);
            rsum = q3 + __shfl_xor_sync(0xffffffffu, q3, 16);
        }
        // lane holds half-dot for chunk-row (q*16 + (lane&15))
        if (lane < 16) {
            const int row = q * 16 + lane;
            sRedH[rank * 128 + row] = rsum;                     // own copy
            uint32_t la = smem_u32(&sRedH[rank * 128 + row]);
            st_shared_remote_f32(mapa_u32(la, peer), rsum);     // peer copy (same slot)
            mbar_arrive_remote(xbar_peer);                      // release: orders my store
        }
        __syncthreads();   // sync1: own half-scores in smem; hv in regs -> stages dead

        // refill both stages (64 threads each, one row apiece)
        if (tid < 64) {
            if (hcA + NSTAGE < NHC) {
                uint32_t mb = smem_u32(&smbar[sA]);
                mbar_arrive_expect_tx(mb, ROW_BYTES);
                bulk_g2s(smem_u32(buf + sA * STAGE_FLOATS + tid * HH),
                         hb + (size_t)((hcA + NSTAGE) * SROWS + tid) * H_DIM, ROW_BYTES, mb);
            }
        } else if (tid < 128) {
            if (hcB + NSTAGE < NHC) {
                const int i = tid - 64;
                uint32_t mb = smem_u32(&smbar[sB]);
                mbar_arrive_expect_tx(mb, ROW_BYTES);
                bulk_g2s(smem_u32(buf + sB * STAGE_FLOATS + i * HH),
                         hb + (size_t)((hcB + NSTAGE) * SROWS + i) * H_DIM, ROW_BYTES, mb);
            }
        }

        // wait for peer's half-scores (128 remote arrivals this phase)
        mbar_wait_parity_cluster(xbar_local, (uint32_t)(g & 1));

        // ---- scan: warp 0, lane owns rows 4*lane..4*lane+3 ----
        if (q == 0) {
            const float4 A  = ((const float4*)sRedH)[lane];          // half 0
            const float4 Bv = ((const float4*)(sRedH + 128))[lane];  // half 1
            float e0 = __expf(A.x + Bv.x + bias);
            float e1 = __expf(A.y + Bv.y + bias);
            float e2 = __expf(A.z + Bv.z + bias);
            float e3 = __expf(A.w + Bv.w + bias);
            float c0 = e0, c1 = c0 + e1, c2 = c1 + e2, c3 = c2 + e3;
            float inc = c3;
            #pragma unroll
            for (int o = 1; o < 32; o <<= 1) {
                float n = __shfl_up_sync(0xffffffffu, inc, o);
                if (lane >= o) inc += n;
            }
            float base = carry + (inc - c3);
            sE4[lane] = make_float4(e0, e1, e2, e3);
            sR4[lane] = make_float4(1.0f / (base + c0 + 1e-12f),
                                    1.0f / (base + c1 + 1e-12f),
                                    1.0f / (base + c2 + 1e-12f),
                                    1.0f / (base + c3 + 1e-12f));
            carry += __shfl_sync(0xffffffffu, inc, 31);
        }
        __syncthreads();   // sync2: e/r ready

        // ---- E1: group partial S_q = sum_k e[16q+k] * hv[k] ----
        float4 S = make_float4(0.f, 0.f, 0.f, 0.f);
        #pragma unroll
        for (int kk = 0; kk < 4; kk++) {
            const float4 e4 = sE4[4 * q + kk];       // broadcast LDS
            S.x = fmaf(e4.x, hv[4*kk+0].x, S.x); S.y = fmaf(e4.x, hv[4*kk+0].y, S.y);
            S.z = fmaf(e4.x, hv[4*kk+0].z, S.z); S.w = fmaf(e4.x, hv[4*kk+0].w, S.w);
            S.x = fmaf(e4.y, hv[4*kk+1].x, S.x); S.y = fmaf(e4.y, hv[4*kk+1].y, S.y);
            S.z = fmaf(e4.y, hv[4*kk+1].z, S.z); S.w = fmaf(e4.y, hv[4*kk+1].w, S.w);
            S.x = fmaf(e4.z, hv[4*kk+2].x, S.x); S.y = fmaf(e4.z, hv[4*kk+2].y, S.y);
            S.z = fmaf(e4.z, hv[4*kk+2].z, S.z); S.w = fmaf(e4.z, hv[4*kk+2].w, S.w);
            S.x = fmaf(e4.w, hv[4*kk+3].x, S.x); S.y = fmaf(e4.w, hv[4*kk+3].y, S.y);
            S.z = fmaf(e4.w, hv[4*kk+3].z, S.z); S.w = fmaf(e4.w, hv[4*kk+3].w, S.w);
        }
        sPart4[q * HH4 + lane] = S;
        __syncthreads();   // sync3: partials ready

        // ---- E2: prefix offset + emit 16 rows (float4 streaming stores) ----
        {
            float4 a = accP;
            #pragma unroll
            for (int i = 0; i < 8; i++) {
                const float4 pi = sPart4[i * HH4 + lane];
                if (i < q) { a.x += pi.x; a.y += pi.y; a.z += pi.z; a.w += pi.w; }
                accP.x += pi.x; accP.y += pi.y; accP.z += pi.z; accP.w += pi.w;
            }
            float4* outg = ob4 + (size_t)(g * CHUNK) * (H_DIM / 4);
            #pragma unroll
            for (int kk = 0; kk < 4; kk++) {
                const float4 e4 = sE4[4 * q + kk];
                const float4 r4 = sR4[4 * q + kk];
                #pragma unroll
                for (int c = 0; c < 4; c++) {
                    const int k = 4 * kk + c;
                    const float ek = (c == 0) ? e4.x : (c == 1) ? e4.y : (c == 2) ? e4.z : e4.w;
                    const float rk = (c == 0) ? r4.x : (c == 1) ? r4.y : (c == 2) ? r4.z : r4.w;
                    a.x = fmaf(ek, hv[k].x, a.x);
                    a.y = fmaf(ek, hv[k].y, a.y);
                    a.z = fmaf(ek, hv[k].z, a.z);
                    a.w = fmaf(ek, hv[k].w, a.w);
                    float4 o4;
                    o4.x = fmaf(a.x, rk, hv[k].x);
                    o4.y = fmaf(a.y, rk, hv[k].y);
                    o4.z = fmaf(a.z, rk, hv[k].z);
                    o4.w = fmaf(a.w, rk, hv[k].w);
                    __stcs(outg + (16 * q + k) * (H_DIM / 4) + lane, o4);
                }
            }
        }
        // no trailing sync: next chunk's sync1 orders sRedH/sE/sR/sPart reuse,
        // and the xbar phase ordering bounds the peer to <=1 chunk ahead.
    }

    // cluster teardown: no CTA exits while peer DSMEM traffic could be in flight
    asm volatile("barrier.cluster.arrive.aligned;" ::: "memory");
    asm volatile("barrier.cluster.wait.aligned;" ::: "memory");
}

extern "C" void kernel_launch(void* const* d_in, const int* in_sizes, int n_in,
                              void* d_out, int out_size) {
    const float* h      = (const float*)d_in[0]; // [8,16,1024,256] f32
    const float* attn_w = (const float*)d_in[1]; // [256] f32
    const float* attn_b = (const float*)d_in[2]; // [1] f32
    float* out = (float*)d_out;
    (void)in_sizes; (void)n_in; (void)out_size;

    cudaFuncSetAttribute(temporal_attn_causal_kernel,
                         cudaFuncAttributeMaxDynamicSharedMemorySize, SMEM_BYTES);
    temporal_attn_causal_kernel<<<256, NTHREADS, SMEM_BYTES>>>(h, attn_w, attn_b, out);
}

// round 16
// speedup vs baseline: 1.1142x; 1.1142x over previous
#include <cuda_runtime.h>
#include <cstdint>
#include <math.h>

#define T_DIM   1024
#define H_DIM   256
#define NTHREADS 512
#define CHUNK   128               // t-rows per compute chunk
#define NCHUNK  (T_DIM / CHUNK)   // 8
#define NSTAGE  3                 // 64-row memory stages
#define SROWS   64                // rows per stage
#define NHC     (T_DIM / SROWS)   // 16 half-chunks

#define STAGE_FLOATS (SROWS * H_DIM)     // 16384 floats = 64 KB
#define STAGE_BYTES  (STAGE_FLOATS * 4)

// smem: buf[NSTAGE][SROWS][H] | sRed[16][16] | sR[128] | sPart[8][64]f4 | mbar
#define SMEM_FLOATS (NSTAGE * STAGE_FLOATS + 256 + 128 + 8 * 64 * 4)
#define SMEM_BYTES  (SMEM_FLOATS * 4 + NSTAGE * 8)

__device__ __forceinline__ uint32_t smem_u32(const void* p) {
    uint32_t a;
    asm("{ .reg .u64 t; cvta.to.shared.u64 t, %1; cvt.u32.u64 %0, t; }" : "=r"(a) : "l"(p));
    return a;
}
__device__ __forceinline__ void mbar_init(uint32_t mbar, uint32_t count) {
    asm volatile("mbarrier.init.shared.b64 [%0], %1;" :: "r"(mbar), "r"(count) : "memory");
}
__device__ __forceinline__ void mbar_expect_tx(uint32_t mbar, uint32_t bytes) {
    asm volatile("mbarrier.arrive.expect_tx.shared.b64 _, [%0], %1;" :: "r"(mbar), "r"(bytes) : "memory");
}
__device__ __forceinline__ void bulk_g2s(uint32_t dst, const void* src, uint32_t bytes, uint32_t mbar) {
    asm volatile("cp.async.bulk.shared::cta.global.mbarrier::complete_tx::bytes [%0], [%1], %2, [%3];"
                 :: "r"(dst), "l"(src), "r"(bytes), "r"(mbar) : "memory");
}
__device__ __forceinline__ void mbar_wait_parity(uint32_t mbar, uint32_t parity) {
    uint32_t done;
    asm volatile(
        "{\n\t.reg .pred p;\n\t"
        "mbarrier.try_wait.parity.acquire.cta.shared::cta.b64 p, [%1], %2;\n\t"
        "selp.b32 %0, 1, 0, p;\n\t}"
        : "=r"(done) : "r"(mbar), "r"(parity) : "memory");
    if (!done) {
        asm volatile(
            "{\n\t.reg .pred P1;\n\t"
            "WL_%=:\n\t"
            "mbarrier.try_wait.parity.acquire.cta.shared::cta.b64 P1, [%0], %1, 0x989680;\n\t"
            "@P1 bra.uni WD_%=;\n\t"
            "bra.uni WL_%=;\n\t"
            "WD_%=:\n\t}"
            :: "r"(mbar), "r"(parity) : "memory");
    }
}

__global__ __launch_bounds__(NTHREADS, 1)
void temporal_attn_causal_kernel(const float* __restrict__ h,
                                 const float* __restrict__ attn_w,
                                 const float* __restrict__ attn_b,
                                 float* __restrict__ out) {
    extern __shared__ __align__(16) unsigned char smem_raw[];
    float*    buf    = (float*)smem_raw;                     // NSTAGE stage tiles
    float*    sRed   = buf + NSTAGE * STAGE_FLOATS;          // [16 warps][16 k]
    float4*   sR4    = (float4*)(sRed + 256);                // r, 32 quads (128 vals)
    float4*   sPart4 = sR4 + 32;                             // [8 q][64 d]
    uint64_t* mbar   = (uint64_t*)(sPart4 + 8 * 64);

    const int bl   = blockIdx.x;        // one CTA per (b,l): 128
    const int tid  = threadIdx.x;
    const int lane = tid & 31;
    const int warp = tid >> 5;
    const int q    = tid >> 6;          // t-group 0..7 (16 rows each)
    const int d    = tid & 63;          // float4 dim slot (dims 4d..4d+3)

    const float* __restrict__ hb = h + (size_t)bl * T_DIM * H_DIM;
    float* __restrict__ ob = out + (size_t)bl * T_DIM * H_DIM;

    const float4 wv = ((const float4*)attn_w)[d];
    const float bias = attn_b[0];

    if (tid == 0) {
        #pragma unroll
        for (int s = 0; s < NSTAGE; s++) mbar_init(smem_u32(&mbar[s]), 1);
        asm volatile("fence.proxy.async.shared::cta;" ::: "memory");
    }
    __syncthreads();
    if (tid == 0) {
        #pragma unroll
        for (int s = 0; s < NSTAGE; s++) {          // prologue: hc 0,1,2
            uint32_t mb = smem_u32(&mbar[s]);
            mbar_expect_tx(mb, STAGE_BYTES);
            bulk_g2s(smem_u32(buf + s * STAGE_FLOATS),
                     hb + (size_t)s * STAGE_FLOATS, STAGE_BYTES, mb);
        }
    }
    __syncthreads();

    float carry = 0.f;                               // scan carry (warp 0)
    float4 accP = make_float4(0.f, 0.f, 0.f, 0.f);   // running acc (replicated)

    for (int g = 0; g < NCHUNK; g++) {
        const int hcA = 2 * g, hcB = 2 * g + 1;
        const int sA = hcA % 3, sB = hcB % 3;
        mbar_wait_parity(smem_u32(&mbar[sA]), (uint32_t)((hcA / 3) & 1));
        mbar_wait_parity(smem_u32(&mbar[sB]), (uint32_t)((hcB / 3) & 1));

        // ---- load my 16 rows x float4 into registers + dot4 partials ----
        const float4* myBase = (const float4*)(buf + (q < 4 ? sA : sB) * STAGE_FLOATS);
        const int rowBase = (q & 3) * 16;
        float4 hv[16];
        float  p[16];
        #pragma unroll
        for (int k = 0; k < 16; k++) {
            hv[k] = myBase[(rowBase + k) * (H_DIM / 4) + d];
            p[k] = hv[k].x * wv.x + hv[k].y * wv.y + hv[k].z * wv.z + hv[k].w * wv.w;
        }

        // ---- butterfly fold: reduce 16 k-partials over 32 lanes (d within warp) ----
        {
            const int b0 = lane & 1, b1 = (lane >> 1) & 1,
                      b2 = (lane >> 2) & 1, b3 = (lane >> 3) & 1;
            float q0[8];
            #pragma unroll
            for (int j = 0; j < 8; j++) {
                float keep = b0 ? p[2*j+1] : p[2*j];
                float send = b0 ? p[2*j]   : p[2*j+1];
                q0[j] = keep + __shfl_xor_sync(0xffffffffu, send, 1);
            }
            float q1[4];
            #pragma unroll
            for (int j = 0; j < 4; j++) {
                float keep = b1 ? q0[2*j+1] : q0[2*j];
                float send = b1 ? q0[2*j]   : q0[2*j+1];
                q1[j] = keep + __shfl_xor_sync(0xffffffffu, send, 2);
            }
            float q2[2];
            #pragma unroll
            for (int j = 0; j < 2; j++) {
                float keep = b2 ? q1[2*j+1] : q1[2*j];
                float send = b2 ? q1[2*j]   : q1[2*j+1];
                q2[j] = keep + __shfl_xor_sync(0xffffffffu, send, 4);
            }
            float keep = b3 ? q2[1] : q2[0];
            float send = b3 ? q2[0] : q2[1];
            float q3 = keep + __shfl_xor_sync(0xffffffffu, send, 8);
            float rsum = q3 + __shfl_xor_sync(0xffffffffu, q3, 16);
            // lane holds row-partial for k = lane&15 over this warp's 32 d-slots
            if (lane < 16) sRed[warp * 16 + lane] = rsum;
        }
        __syncthreads();   // sync1: sRed ready; hv in regs -> stages dead

        // refill both stages now (earliest possible point)
        if (tid == 0) {
            if (hcA + 3 < NHC) {
                uint32_t mb = smem_u32(&mbar[sA]);
                mbar_expect_tx(mb, STAGE_BYTES);
                bulk_g2s(smem_u32(buf + sA * STAGE_FLOATS),
                         hb + (size_t)(hcA + 3) * STAGE_FLOATS, STAGE_BYTES, mb);
            }
            if (hcB + 3 < NHC) {
                uint32_t mb = smem_u32(&mbar[sB]);
                mbar_expect_tx(mb, STAGE_BYTES);
                bulk_g2s(smem_u32(buf + sB * STAGE_FLOATS),
                         hb + (size_t)(hcB + 3) * STAGE_FLOATS, STAGE_BYTES, mb);
            }
        }

        // ---- per-warp e for its 16 rows (no scan dependency!) ----
        // lane k (k<16) computes e of row 16q+k; lanes 16-31 duplicate (k&15).
        float eLane;
        {
            const int k = lane & 15;
            const float s0 = sRed[32 * q + k];        // warp 2q partial (dims 0-127 half)
            const float s1 = sRed[32 * q + 16 + k];   // warp 2q+1 partial
            eLane = __expf(s0 + s1 + bias);
        }

        // ---- E1: group partial S_q[d] = sum_k e[16q+k] * hv[k] ----
        float4 S = make_float4(0.f, 0.f, 0.f, 0.f);
        #pragma unroll
        for (int k = 0; k < 16; k++) {
            const float ek = __shfl_sync(0xffffffffu, eLane, k);
            S.x = fmaf(ek, hv[k].x, S.x);
            S.y = fmaf(ek, hv[k].y, S.y);
            S.z = fmaf(ek, hv[k].z, S.z);
            S.w = fmaf(ek, hv[k].w, S.w);
        }
        sPart4[q * 64 + d] = S;

        // ---- scan r: warp 0 only, concurrent with other warps' E1 ----
        if (warp == 0) {
            const int qq = lane >> 2;                // t-group of this quad
            const int kk = lane & 3;                 // k-quad within group
            const float4* red4 = (const float4*)sRed;
            float4 A = red4[(2*qq)     * 4 + kk];
            float4 B = red4[(2*qq + 1) * 4 + kk];
            // identical op order to eLane: (s0 + s1) + bias
            float e0 = __expf(A.x + B.x + bias);
            float e1 = __expf(A.y + B.y + bias);
            float e2 = __expf(A.z + B.z + bias);
            float e3 = __expf(A.w + B.w + bias);
            float c0 = e0, c1 = c0 + e1, c2 = c1 + e2, c3 = c2 + e3;
            float inc = c3;
            #pragma unroll
            for (int o = 1; o < 32; o <<= 1) {
                float n = __shfl_up_sync(0xffffffffu, inc, o);
                if (lane >= o) inc += n;
            }
            float base = carry + (inc - c3);
            sR4[lane] = make_float4(1.0f / (base + c0 + 1e-12f),
                                    1.0f / (base + c1 + 1e-12f),
                                    1.0f / (base + c2 + 1e-12f),
                                    1.0f / (base + c3 + 1e-12f));
            carry += __shfl_sync(0xffffffffu, inc, 31);
        }
        __syncthreads();   // sync2: partials + r ready

        // ---- E2: prefix offset + emit 16 rows ----
        {
            float4 a = accP;
            #pragma unroll
            for (int i = 0; i < 8; i++) {            // stream partials
                const float4 pi = sPart4[i * 64 + d];
                if (i < q) { a.x += pi.x; a.y += pi.y; a.z += pi.z; a.w += pi.w; }
                accP.x += pi.x; accP.y += pi.y; accP.z += pi.z; accP.w += pi.w;
            }
            float4* outg = (float4*)(ob + (size_t)g * CHUNK * H_DIM);
            #pragma unroll
            for (int kk = 0; kk < 4; kk++) {
                const float4 r4 = sR4[4*q + kk];
                #pragma unroll
                for (int c = 0; c < 4; c++) {
                    const int k = 4*kk + c;
                    const float ek = __shfl_sync(0xffffffffu, eLane, k);
                    const float rk = (c == 0) ? r4.x : (c == 1) ? r4.y : (c == 2) ? r4.z : r4.w;
                    a.x = fmaf(ek, hv[k].x, a.x);
                    a.y = fmaf(ek, hv[k].y, a.y);
                    a.z = fmaf(ek, hv[k].z, a.z);
                    a.w = fmaf(ek, hv[k].w, a.w);
                    float4 o4;
                    o4.x = fmaf(a.x, rk, hv[k].x);
                    o4.y = fmaf(a.y, rk, hv[k].y);
                    o4.z = fmaf(a.z, rk, hv[k].z);
                    o4.w = fmaf(a.w, rk, hv[k].w);
                    __stcs(outg + (16*q + k) * (H_DIM / 4) + d, o4);
                }
            }
        }
        // no trailing sync: next chunk's sync1/sync2 order sRed/sR/sPart reuse
        // (sRed(g+1) writes happen pre-sync1(g+1), which all warps reach only
        //  after E2(g); sRed(g) reads complete before sync2(g).)
    }
}

extern "C" void kernel_launch(void* const* d_in, const int* in_sizes, int n_in,
                              void* d_out, int out_size) {
    const float* h      = (const float*)d_in[0]; // [8,16,1024,256] f32
    const float* attn_w = (const float*)d_in[1]; // [256] f32
    const float* attn_b = (const float*)d_in[2]; // [1] f32
    float* out = (float*)d_out;
    (void)in_sizes; (void)n_in; (void)out_size;

    cudaFuncSetAttribute(temporal_attn_causal_kernel,
                         cudaFuncAttributeMaxDynamicSharedMemorySize, SMEM_BYTES);
    temporal_attn_causal_kernel<<<128, NTHREADS, SMEM_BYTES>>>(h, attn_w, attn_b, out);
}

// round 17
// speedup vs baseline: 1.1236x; 1.0085x over previous
#include <cuda_runtime.h>
#include <cstdint>
#include <math.h>

#define T_DIM   1024
#define H_DIM   256
#define NTHREADS 512
#define CHUNK   128               // t-rows per compute chunk
#define NCHUNK  (T_DIM / CHUNK)   // 8
#define NSTAGE  6                 // 32-row memory stages (ring)
#define SROWS   32                // rows per stage
#define NHC     (T_DIM / SROWS)   // 32 sub-chunks

#define STAGE_FLOATS (SROWS * H_DIM)     // 8192 floats = 32 KB
#define STAGE_BYTES  (STAGE_FLOATS * 4)

// smem: buf[NSTAGE][SROWS][H] | sRed[16][16] | sR[128] | sPart[8][64]f4 | mbar
#define SMEM_FLOATS (NSTAGE * STAGE_FLOATS + 256 + 128 + 8 * 64 * 4)
#define SMEM_BYTES  (SMEM_FLOATS * 4 + NSTAGE * 8)

__device__ __forceinline__ uint32_t smem_u32(const void* p) {
    uint32_t a;
    asm("{ .reg .u64 t; cvta.to.shared.u64 t, %1; cvt.u32.u64 %0, t; }" : "=r"(a) : "l"(p));
    return a;
}
__device__ __forceinline__ void mbar_init(uint32_t mbar, uint32_t count) {
    asm volatile("mbarrier.init.shared.b64 [%0], %1;" :: "r"(mbar), "r"(count) : "memory");
}
__device__ __forceinline__ void mbar_expect_tx(uint32_t mbar, uint32_t bytes) {
    asm volatile("mbarrier.arrive.expect_tx.shared.b64 _, [%0], %1;" :: "r"(mbar), "r"(bytes) : "memory");
}
__device__ __forceinline__ void bulk_g2s(uint32_t dst, const void* src, uint32_t bytes, uint32_t mbar) {
    asm volatile("cp.async.bulk.shared::cta.global.mbarrier::complete_tx::bytes [%0], [%1], %2, [%3];"
                 :: "r"(dst), "l"(src), "r"(bytes), "r"(mbar) : "memory");
}
__device__ __forceinline__ void mbar_wait_parity(uint32_t mbar, uint32_t parity) {
    uint32_t done;
    asm volatile(
        "{\n\t.reg .pred p;\n\t"
        "mbarrier.try_wait.parity.acquire.cta.shared::cta.b64 p, [%1], %2;\n\t"
        "selp.b32 %0, 1, 0, p;\n\t}"
        : "=r"(done) : "r"(mbar), "r"(parity) : "memory");
    if (!done) {
        asm volatile(
            "{\n\t.reg .pred P1;\n\t"
            "WL_%=:\n\t"
            "mbarrier.try_wait.parity.acquire.cta.shared::cta.b64 P1, [%0], %1, 0x989680;\n\t"
            "@P1 bra.uni WD_%=;\n\t"
            "bra.uni WL_%=;\n\t"
            "WD_%=:\n\t}"
            :: "r"(mbar), "r"(parity) : "memory");
    }
}

__global__ __launch_bounds__(NTHREADS, 1)
void temporal_attn_causal_kernel(const float* __restrict__ h,
                                 const float* __restrict__ attn_w,
                                 const float* __restrict__ attn_b,
                                 float* __restrict__ out) {
    extern __shared__ __align__(16) unsigned char smem_raw[];
    float*    buf    = (float*)smem_raw;                     // NSTAGE stage tiles
    float*    sRed   = buf + NSTAGE * STAGE_FLOATS;          // [16 warps][16 k]
    float4*   sR4    = (float4*)(sRed + 256);                // r, 32 quads (128 vals)
    float4*   sPart4 = sR4 + 32;                             // [8 q][64 d]
    uint64_t* mbar   = (uint64_t*)(sPart4 + 8 * 64);

    const int bl   = blockIdx.x;        // one CTA per (b,l): 128
    const int tid  = threadIdx.x;
    const int lane = tid & 31;
    const int warp = tid >> 5;
    const int q    = tid >> 6;          // t-group 0..7 (16 rows each)
    const int d    = tid & 63;          // float4 dim slot (dims 4d..4d+3)
    const int j    = q >> 1;            // sub-chunk (stage) index 0..3 for this warp

    const float* __restrict__ hb = h + (size_t)bl * T_DIM * H_DIM;
    float* __restrict__ ob = out + (size_t)bl * T_DIM * H_DIM;

    const float4 wv = ((const float4*)attn_w)[d];
    const float bias = attn_b[0];

    if (tid == 0) {
        #pragma unroll
        for (int s = 0; s < NSTAGE; s++) mbar_init(smem_u32(&mbar[s]), 1);
        asm volatile("fence.proxy.async.shared::cta;" ::: "memory");
    }
    __syncthreads();
    // prologue: threads 0..5 each fill one stage (hc 0..5)
    if (tid < NSTAGE) {
        uint32_t mb = smem_u32(&mbar[tid]);
        mbar_expect_tx(mb, STAGE_BYTES);
        bulk_g2s(smem_u32(buf + tid * STAGE_FLOATS),
                 hb + (size_t)tid * STAGE_FLOATS, STAGE_BYTES, mb);
    }
    __syncthreads();

    float carry = 0.f;                               // scan carry (warp 0)
    float4 accP = make_float4(0.f, 0.f, 0.f, 0.f);   // running acc (replicated)

    for (int g = 0; g < NCHUNK; g++) {
        // ---- per-warp wait: only the stage this warp reads ----
        const int hc = 4 * g + j;
        const int st = hc % NSTAGE;
        mbar_wait_parity(smem_u32(&mbar[st]), (uint32_t)((hc / NSTAGE) & 1));

        // ---- load my 16 rows x float4 into registers + dot4 partials ----
        const float4* myBase = (const float4*)(buf + st * STAGE_FLOATS);
        const int rowBase = (q & 1) * 16;
        float4 hv[16];
        float  p[16];
        #pragma unroll
        for (int k = 0; k < 16; k++) {
            hv[k] = myBase[(rowBase + k) * (H_DIM / 4) + d];
            p[k] = hv[k].x * wv.x + hv[k].y * wv.y + hv[k].z * wv.z + hv[k].w * wv.w;
        }

        // ---- butterfly fold: reduce 16 k-partials over 32 lanes (d within warp) ----
        {
            const int b0 = lane & 1, b1 = (lane >> 1) & 1,
                      b2 = (lane >> 2) & 1, b3 = (lane >> 3) & 1;
            float q0[8];
            #pragma unroll
            for (int jj = 0; jj < 8; jj++) {
                float keep = b0 ? p[2*jj+1] : p[2*jj];
                float send = b0 ? p[2*jj]   : p[2*jj+1];
                q0[jj] = keep + __shfl_xor_sync(0xffffffffu, send, 1);
            }
            float q1[4];
            #pragma unroll
            for (int jj = 0; jj < 4; jj++) {
                float keep = b1 ? q0[2*jj+1] : q0[2*jj];
                float send = b1 ? q0[2*jj]   : q0[2*jj+1];
                q1[jj] = keep + __shfl_xor_sync(0xffffffffu, send, 2);
            }
            float q2[2];
            #pragma unroll
            for (int jj = 0; jj < 2; jj++) {
                float keep = b2 ? q1[2*jj+1] : q1[2*jj];
                float send = b2 ? q1[2*jj]   : q1[2*jj+1];
                q2[jj] = keep + __shfl_xor_sync(0xffffffffu, send, 4);
            }
            float keep = b3 ? q2[1] : q2[0];
            float send = b3 ? q2[0] : q2[1];
            float q3 = keep + __shfl_xor_sync(0xffffffffu, send, 8);
            float rsum = q3 + __shfl_xor_sync(0xffffffffu, q3, 16);
            // lane holds row-partial for k = lane&15 over this warp's 32 d-slots
            if (lane < 16) sRed[warp * 16 + lane] = rsum;
        }
        __syncthreads();   // sync1: sRed ready; hv in regs -> all 4 stages dead

        // refill the 4 freed stages (threads 0..3, one 32KB copy each)
        if (tid < 4) {
            const int hcr = 4 * g + tid + NSTAGE;    // next data for freed stage
            if (hcr < NHC) {
                const int sr = (4 * g + tid) % NSTAGE;
                uint32_t mb = smem_u32(&mbar[sr]);
                mbar_expect_tx(mb, STAGE_BYTES);
                bulk_g2s(smem_u32(buf + sr * STAGE_FLOATS),
                         hb + (size_t)hcr * STAGE_FLOATS, STAGE_BYTES, mb);
            }
        }

        // ---- per-warp e for its 16 rows (no scan dependency) ----
        float eLane;
        {
            const int k = lane & 15;
            const float s0 = sRed[32 * q + k];        // warp 2q partial (dims 0-127)
            const float s1 = sRed[32 * q + 16 + k];   // warp 2q+1 partial (dims 128-255)
            eLane = __expf(s0 + s1 + bias);
        }

        // ---- E1: group partial S_q[d] = sum_k e[16q+k] * hv[k] ----
        float4 S = make_float4(0.f, 0.f, 0.f, 0.f);
        #pragma unroll
        for (int k = 0; k < 16; k++) {
            const float ek = __shfl_sync(0xffffffffu, eLane, k);
            S.x = fmaf(ek, hv[k].x, S.x);
            S.y = fmaf(ek, hv[k].y, S.y);
            S.z = fmaf(ek, hv[k].z, S.z);
            S.w = fmaf(ek, hv[k].w, S.w);
        }
        sPart4[q * 64 + d] = S;

        // ---- scan r: warp 0 only, concurrent with other warps' E1 ----
        if (warp == 0) {
            const int qq = lane >> 2;                // t-group of this quad
            const int kk = lane & 3;                 // k-quad within group
            const float4* red4 = (const float4*)sRed;
            float4 A = red4[(2*qq)     * 4 + kk];
            float4 B = red4[(2*qq + 1) * 4 + kk];
            // identical op order to eLane: (s0 + s1) + bias
            float e0 = __expf(A.x + B.x + bias);
            float e1 = __expf(A.y + B.y + bias);
            float e2 = __expf(A.z + B.z + bias);
            float e3 = __expf(A.w + B.w + bias);
            float c0 = e0, c1 = c0 + e1, c2 = c1 + e2, c3 = c2 + e3;
            float inc = c3;
            #pragma unroll
            for (int o = 1; o < 32; o <<= 1) {
                float n = __shfl_up_sync(0xffffffffu, inc, o);
                if (lane >= o) inc += n;
            }
            float base = carry + (inc - c3);
            sR4[lane] = make_float4(1.0f / (base + c0 + 1e-12f),
                                    1.0f / (base + c1 + 1e-12f),
                                    1.0f / (base + c2 + 1e-12f),
                                    1.0f / (base + c3 + 1e-12f));
            carry += __shfl_sync(0xffffffffu, inc, 31);
        }
        __syncthreads();   // sync2: partials + r ready

        // ---- E2: prefix offset + emit 16 rows ----
        {
            float4 a = accP;
            #pragma unroll
            for (int i = 0; i < 8; i++) {            // stream partials
                const float4 pi = sPart4[i * 64 + d];
                if (i < q) { a.x += pi.x; a.y += pi.y; a.z += pi.z; a.w += pi.w; }
                accP.x += pi.x; accP.y += pi.y; accP.z += pi.z; accP.w += pi.w;
            }
            float4* outg = (float4*)(ob + (size_t)g * CHUNK * H_DIM);
            #pragma unroll
            for (int kk = 0; kk < 4; kk++) {
                const float4 r4 = sR4[4*q + kk];
                #pragma unroll
                for (int c = 0; c < 4; c++) {
                    const int k = 4*kk + c;
                    const float ek = __shfl_sync(0xffffffffu, eLane, k);
                    const float rk = (c == 0) ? r4.x : (c == 1) ? r4.y : (c == 2) ? r4.z : r4.w;
                    a.x = fmaf(ek, hv[k].x, a.x);
                    a.y = fmaf(ek, hv[k].y, a.y);
                    a.z = fmaf(ek, hv[k].z, a.z);
                    a.w = fmaf(ek, hv[k].w, a.w);
                    float4 o4;
                    o4.x = fmaf(a.x, rk, hv[k].x);
                    o4.y = fmaf(a.y, rk, hv[k].y);
                    o4.z = fmaf(a.z, rk, hv[k].z);
                    o4.w = fmaf(a.w, rk, hv[k].w);
                    __stcs(outg + (16*q + k) * (H_DIM / 4) + d, o4);
                }
            }
        }
        // no trailing sync: next chunk's sync1/sync2 order sRed/sR/sPart reuse
    }
}

extern "C" void kernel_launch(void* const* d_in, const int* in_sizes, int n_in,
                              void* d_out, int out_size) {
    const float* h      = (const float*)d_in[0]; // [8,16,1024,256] f32
    const float* attn_w = (const float*)d_in[1]; // [256] f32
    const float* attn_b = (const float*)d_in[2]; // [1] f32
    float* out = (float*)d_out;
    (void)in_sizes; (void)n_in; (void)out_size;

    cudaFuncSetAttribute(temporal_attn_causal_kernel,
                         cudaFuncAttributeMaxDynamicSharedMemorySize, SMEM_BYTES);
    temporal_attn_causal_kernel<<<128, NTHREADS, SMEM_BYTES>>>(h, attn_w, attn_b, out);
}